// round 9
// baseline (speedup 1.0000x reference)
#include <cuda_runtime.h>
#include <cuda_bf16.h>
#include <cstdint>

// out[b, de] = sum_k w[b,k] * A[k, de], A diagonal (de % 257 == 0) zeroed for all k.
// W: (2048, 32) f32   A: (32, 65536) f32   Out: (2048, 65536) f32
//
// mma.sync.m16n8k16 bf16 Karatsuba GEMM (AhWh + AlWh + AhWl), staged coalesced
// epilogue, 3 CTAs/SM:
//   CTA: 256 batch x 128 de.  Warp: 32 batch x 128 de.
//   Per 32-de chunk: two halves of 2 n8-fragments each (16 live accumulators),
//   staged to per-warp smem (stride 40 -> conflict-free), drained as 8 STG.128
//   full 128B lines. __launch_bounds__(256,3) -> <=84 regs, 24 warps/SM.

#define DE   65536
#define KD   32
#define TDE  128     // de per CTA
#define TB   256     // batch per CTA
#define NB   2048
#define ASTRIDE 20   // uint32 row stride for A tiles
#define SSTRIDE 40   // float row stride for staging

// dynamic smem layout (bytes)
#define SM_AH    0
#define SM_AL    (TDE * ASTRIDE * 4)                 // 10240
#define SM_STAGE (2 * TDE * ASTRIDE * 4)             // 20480
#define SM_TOTAL (SM_STAGE + 8 * 32 * SSTRIDE * 4)   // 61440

static __device__ __forceinline__ uint32_t pack_bf16x2(float e0, float e1) {
    __nv_bfloat16 a = __float2bfloat16(e0);
    __nv_bfloat16 b = __float2bfloat16(e1);
    return (uint32_t)__bfloat16_as_ushort(a) | ((uint32_t)__bfloat16_as_ushort(b) << 16);
}

static __device__ __forceinline__ void mma16816(float* d, const uint32_t* a,
                                                uint32_t b0, uint32_t b1) {
    asm volatile(
        "mma.sync.aligned.m16n8k16.row.col.f32.bf16.bf16.f32 "
        "{%0,%1,%2,%3}, {%4,%5,%6,%7}, {%8,%9}, {%0,%1,%2,%3};"
        : "+f"(d[0]), "+f"(d[1]), "+f"(d[2]), "+f"(d[3])
        : "r"(a[0]), "r"(a[1]), "r"(a[2]), "r"(a[3]), "r"(b0), "r"(b1));
}

__global__ __launch_bounds__(256, 3)
void explainer_hmma(const float* __restrict__ w,
                    const float* __restrict__ A,
                    float* __restrict__ out) {
    extern __shared__ char smem[];
    uint32_t* Ah = (uint32_t*)(smem + SM_AH);
    uint32_t* Al = (uint32_t*)(smem + SM_AL);

    const int tid = threadIdx.x;
    const int de0 = blockIdx.x * TDE;
    const int b0  = blockIdx.y * TB;

    // ---- Load A tile: 128 de x 16 k-pairs; split hi/lo bf16 ----
    #pragma unroll
    for (int i = 0; i < 8; i++) {
        int idx = tid + i * 256;        // 0..2047
        int p   = idx >> 7;             // k-pair 0..15
        int de  = idx & 127;
        int k0  = p << 1;
        float v0 = A[(size_t)k0 * DE + de0 + de];
        float v1 = A[(size_t)(k0 + 1) * DE + de0 + de];
        if (((de0 + de) % 257) == 0) { v0 = 0.0f; v1 = 0.0f; }
        float h0 = __bfloat162float(__float2bfloat16(v0));
        float h1 = __bfloat162float(__float2bfloat16(v1));
        Ah[de * ASTRIDE + p] = pack_bf16x2(h0, h1);
        Al[de * ASTRIDE + p] = pack_bf16x2(v0 - h0, v1 - h1);
    }

    // ---- W fragments in registers: warp covers 32 batches (2 m16 groups) ----
    const int warp = tid >> 5;
    const int lane = tid & 31;
    const int qr = lane >> 2;   // 0..7
    const int qc = lane & 3;    // 0..3
    const int mb = b0 + warp * 32;

    uint32_t whi[2][2][4], wlo[2][2][4];   // [m-group][k-step][a-reg]
    #pragma unroll
    for (int g = 0; g < 2; g++) {
        #pragma unroll
        for (int s = 0; s < 2; s++) {
            #pragma unroll
            for (int h = 0; h < 2; h++) {
                #pragma unroll
                for (int rr = 0; rr < 2; rr++) {
                    int row = mb + g * 16 + qr + rr * 8;
                    int kk  = s * 16 + 2 * qc + h * 8;
                    float2 v = *(const float2*)&w[(size_t)row * KD + kk];
                    float hx = __bfloat162float(__float2bfloat16(v.x));
                    float hy = __bfloat162float(__float2bfloat16(v.y));
                    int reg = rr + 2 * h;
                    whi[g][s][reg] = pack_bf16x2(hx, hy);
                    wlo[g][s][reg] = pack_bf16x2(v.x - hx, v.y - hy);
                }
            }
        }
    }
    __syncthreads();

    float* Sw = (float*)(smem + SM_STAGE) + warp * 32 * SSTRIDE;
    const int rsub = lane >> 3;   // 0..3
    const int c8   = lane & 7;    // 0..7

    // ---- 4 chunks of 32 de; each chunk = 2 halves of 2 n8-fragments ----
    #pragma unroll 1
    for (int c = 0; c < 4; c++) {
        #pragma unroll
        for (int h = 0; h < 2; h++) {
            float dd[2][2][4];

            #pragma unroll
            for (int f = 0; f < 2; f++) {
                int fc = c * 4 + h * 2 + f;
                const uint32_t* ar = &Ah[(fc * 8 + qr) * ASTRIDE];
                const uint32_t* al = &Al[(fc * 8 + qr) * ASTRIDE];
                uint32_t bh00 = ar[qc],     bh01 = ar[qc + 4];
                uint32_t bh10 = ar[8 + qc], bh11 = ar[12 + qc];
                uint32_t bl00 = al[qc],     bl01 = al[qc + 4];
                uint32_t bl10 = al[8 + qc], bl11 = al[12 + qc];

                #pragma unroll
                for (int g = 0; g < 2; g++) {
                    dd[f][g][0] = 0.f; dd[f][g][1] = 0.f;
                    dd[f][g][2] = 0.f; dd[f][g][3] = 0.f;
                    mma16816(dd[f][g], whi[g][0], bh00, bh01);
                    mma16816(dd[f][g], whi[g][1], bh10, bh11);
                    mma16816(dd[f][g], wlo[g][0], bh00, bh01);
                    mma16816(dd[f][g], wlo[g][1], bh10, bh11);
                    mma16816(dd[f][g], whi[g][0], bl00, bl01);
                    mma16816(dd[f][g], whi[g][1], bl10, bl11);
                }
            }

            // ---- Stage this half: STS.64, conflict-free (stride 40) ----
            #pragma unroll
            for (int f = 0; f < 2; f++) {
                int colf = (h * 2 + f) * 8 + 2 * qc;
                #pragma unroll
                for (int g = 0; g < 2; g++) {
                    *(float2*)&Sw[(g * 16 + qr) * SSTRIDE + colf] =
                        make_float2(dd[f][g][0], dd[f][g][1]);
                    *(float2*)&Sw[(g * 16 + qr + 8) * SSTRIDE + colf] =
                        make_float2(dd[f][g][2], dd[f][g][3]);
                }
            }
        }
        __syncwarp();

        // ---- Drain 32 de: LDS.128 (single row per phase) + STG.128 full lines ----
        #pragma unroll
        for (int i = 0; i < 8; i++) {
            int r = i * 4 + rsub;
            float4 v = *(const float4*)&Sw[r * SSTRIDE + c8 * 4];
            __stcs((float4*)&out[(size_t)(mb + r) * DE + de0 + c * 32 + c8 * 4], v);
        }
        __syncwarp();
    }
}

extern "C" void kernel_launch(void* const* d_in, const int* in_sizes, int n_in,
                              void* d_out, int out_size) {
    const float* w = (const float*)d_in[0];   // batch_weights (2048, 32)
    const float* A = (const float*)d_in[1];   // archs (32, 256, 256)
    float* out = (float*)d_out;               // (2048, 256, 256) f32

    cudaFuncSetAttribute(explainer_hmma, cudaFuncAttributeMaxDynamicSharedMemorySize,
                         SM_TOTAL);
    dim3 grid(DE / TDE, NB / TB);             // (512, 8)
    explainer_hmma<<<grid, 256, SM_TOTAL>>>(w, A, out);
}

// round 10
// speedup vs baseline: 1.2849x; 1.2849x over previous
#include <cuda_runtime.h>
#include <cuda_fp16.h>
#include <cstdint>

// out[b, de] = sum_k w[b,k] * A[k, de], A diagonal (de % 257 == 0) zeroed for all k.
// W: (2048, 32) f32   A: (32, 65536) f32   Out: (2048, 65536) f32
//
// Single-product fp16 HMMA (m16n8k16.f32.f16.f16.f32), fp32 accumulate.
// Norm rel_err ~4e-4 (inputs N(0,1), K=32) — under the 1e-3 gate.
//   CTA: 256 batch x 128 de, 8 warps; warp: 32 batch x 128 de.
//   Full 4-fragment chunks (32 de), staged coalesced epilogue (stride-40 smem,
//   conflict-free STS.64/LDS.128, STG.128 full 128B lines).
//   3 CTAs/SM: regs <= 84, smem 50KB/CTA.

#define DE   65536
#define KD   32
#define TDE  128     // de per CTA
#define TB   256     // batch per CTA
#define NB   2048
#define ASTRIDE 20   // uint32 row stride for A tile (conflict-free LDS.32)
#define SSTRIDE 40   // float row stride for staging (conflict-free STS.64/LDS.128)

// dynamic smem layout (bytes)
#define SM_AH    0
#define SM_STAGE (TDE * ASTRIDE * 4)                 // 10240
#define SM_TOTAL (SM_STAGE + 8 * 32 * SSTRIDE * 4)   // 51200

static __device__ __forceinline__ uint32_t pack_h2(float e0, float e1) {
    __half2 h = __floats2half2_rn(e0, e1);
    return *(uint32_t*)&h;
}

static __device__ __forceinline__ void mma16816(float* d, const uint32_t* a,
                                                uint32_t b0, uint32_t b1) {
    asm volatile(
        "mma.sync.aligned.m16n8k16.row.col.f32.f16.f16.f32 "
        "{%0,%1,%2,%3}, {%4,%5,%6,%7}, {%8,%9}, {%0,%1,%2,%3};"
        : "+f"(d[0]), "+f"(d[1]), "+f"(d[2]), "+f"(d[3])
        : "r"(a[0]), "r"(a[1]), "r"(a[2]), "r"(a[3]), "r"(b0), "r"(b1));
}

__global__ __launch_bounds__(256, 3)
void explainer_hmma(const float* __restrict__ w,
                    const float* __restrict__ A,
                    float* __restrict__ out) {
    extern __shared__ char smem[];
    uint32_t* Ah = (uint32_t*)(smem + SM_AH);

    const int tid = threadIdx.x;
    const int de0 = blockIdx.x * TDE;
    const int b0  = blockIdx.y * TB;

    // ---- Load A tile: 128 de x 16 k-pairs, fp16 packed, diagonal masked ----
    #pragma unroll
    for (int i = 0; i < 8; i++) {
        int idx = tid + i * 256;        // 0..2047
        int p   = idx >> 7;             // k-pair 0..15
        int de  = idx & 127;
        int k0  = p << 1;
        float v0 = A[(size_t)k0 * DE + de0 + de];
        float v1 = A[(size_t)(k0 + 1) * DE + de0 + de];
        if (((de0 + de) % 257) == 0) { v0 = 0.0f; v1 = 0.0f; }
        Ah[de * ASTRIDE + p] = pack_h2(v0, v1);
    }

    // ---- W fragments in registers: warp covers 32 batches (2 m16 groups) ----
    const int warp = tid >> 5;
    const int lane = tid & 31;
    const int qr = lane >> 2;   // 0..7
    const int qc = lane & 3;    // 0..3
    const int mb = b0 + warp * 32;

    uint32_t whi[2][2][4];      // [m-group][k-step][a-reg]
    #pragma unroll
    for (int g = 0; g < 2; g++) {
        #pragma unroll
        for (int s = 0; s < 2; s++) {
            #pragma unroll
            for (int h = 0; h < 2; h++) {
                #pragma unroll
                for (int rr = 0; rr < 2; rr++) {
                    int row = mb + g * 16 + qr + rr * 8;
                    int kk  = s * 16 + 2 * qc + h * 8;
                    float2 v = *(const float2*)&w[(size_t)row * KD + kk];
                    whi[g][s][rr + 2 * h] = pack_h2(v.x, v.y);
                }
            }
        }
    }
    __syncthreads();

    float* Sw = (float*)(smem + SM_STAGE) + warp * 32 * SSTRIDE;
    const int rsub = lane >> 3;   // 0..3
    const int c8   = lane & 7;    // 0..7

    // ---- 4 chunks of 4 n8-fragments (32 consecutive de per chunk) ----
    #pragma unroll 1
    for (int c = 0; c < 4; c++) {
        float dd[4][2][4];

        #pragma unroll
        for (int f = 0; f < 4; f++) {
            int fc = c * 4 + f;
            const uint32_t* ar = &Ah[(fc * 8 + qr) * ASTRIDE];
            uint32_t bh00 = ar[qc],     bh01 = ar[qc + 4];
            uint32_t bh10 = ar[8 + qc], bh11 = ar[12 + qc];

            #pragma unroll
            for (int g = 0; g < 2; g++) {
                dd[f][g][0] = 0.f; dd[f][g][1] = 0.f;
                dd[f][g][2] = 0.f; dd[f][g][3] = 0.f;
                mma16816(dd[f][g], whi[g][0], bh00, bh01);   // k-step 0
                mma16816(dd[f][g], whi[g][1], bh10, bh11);   // k-step 1
            }
        }

        // ---- Stage: STS.64, stride 40 -> conflict-free per half-warp phase ----
        #pragma unroll
        for (int f = 0; f < 4; f++) {
            int colf = f * 8 + 2 * qc;
            #pragma unroll
            for (int g = 0; g < 2; g++) {
                *(float2*)&Sw[(g * 16 + qr) * SSTRIDE + colf] =
                    make_float2(dd[f][g][0], dd[f][g][1]);
                *(float2*)&Sw[(g * 16 + qr + 8) * SSTRIDE + colf] =
                    make_float2(dd[f][g][2], dd[f][g][3]);
            }
        }
        __syncwarp();

        // ---- Drain 32 de: LDS.128 (conflict-free) + STG.128 full 128B lines ----
        #pragma unroll
        for (int i = 0; i < 8; i++) {
            int r = i * 4 + rsub;
            float4 v = *(const float4*)&Sw[r * SSTRIDE + c8 * 4];
            __stcs((float4*)&out[(size_t)(mb + r) * DE + de0 + c * 32 + c8 * 4], v);
        }
        __syncwarp();
    }
}

extern "C" void kernel_launch(void* const* d_in, const int* in_sizes, int n_in,
                              void* d_out, int out_size) {
    const float* w = (const float*)d_in[0];   // batch_weights (2048, 32)
    const float* A = (const float*)d_in[1];   // archs (32, 256, 256)
    float* out = (float*)d_out;               // (2048, 256, 256) f32

    cudaFuncSetAttribute(explainer_hmma, cudaFuncAttributeMaxDynamicSharedMemorySize,
                         SM_TOTAL);
    dim3 grid(DE / TDE, NB / TB);             // (512, 8)
    explainer_hmma<<<grid, 256, SM_TOTAL>>>(w, A, out);
}